// round 5
// baseline (speedup 1.0000x reference)
#include <cuda_runtime.h>
#include <math.h>

// Problem dims (fixed by the dataset)
#define NN 50000   // nodes
#define KK 10      // sampled neighbors (sequence length)
#define FF 128     // input_dim
#define HH 64      // hidden per direction
#define GG 256     // 4*H gates
#define MF (NN*KK) // 500000 projection rows (forward)

// Scratch (device globals — no allocation allowed)
__device__ float g_xg [(size_t)MF * GG];  // [N*K, 256] forward input projections (+bias)
__device__ float g_xgb[(size_t)NN * GG];  // [N, 256]   backward-last-step projections (+bias)

__device__ __forceinline__ float sigf(float x) {
    return 1.f / (1.f + __expf(-x));
}
__device__ __forceinline__ float tanh_fast(float x) {
    // tanh(x) = 1 - 2/(e^{2x}+1); robust at +/-inf of exp
    float e = __expf(2.f * x);
    return 1.f - 2.f / (e + 1.f);
}

// ---------------------------------------------------------------------------
// Kernel 1: gathered projection GEMM
//   out[r][g] = sum_f table[idx(r)][f] * Wih[g][f] + bih[g] + bhh[g]
//   fwd: r in [0, N*K), idx(r) = neigh[r],        out = g_xg
//   bwd: r in [0, N),   idx(r) = neigh[r*K+K-1],  out = g_xgb
// Tiling: TM=64 rows, TN=64 gates (gridDim.y=4), TK=64 (2 passes over F=128)
// 256 threads, 4x4 micro-tile, k-major SMEM tiles (vectorized LDS, broadcasts)
// ---------------------------------------------------------------------------
__global__ __launch_bounds__(256) void proj_kernel(
    const int*   __restrict__ neigh,
    const float* __restrict__ table,
    const float* __restrict__ Wih,
    const float* __restrict__ bih,
    const float* __restrict__ bhh,
    int M, int bwd)
{
    __shared__ float As[64][68];  // [k][row]  pad 68 (mult of 4 for LDS.128)
    __shared__ float Bs[64][68];  // [k][gate]

    float* outp = bwd ? g_xgb : g_xg;

    const int tid  = threadIdx.x;
    const int w    = tid >> 5;
    const int l    = tid & 31;
    const int row0 = blockIdx.x * 64;
    const int gate0 = blockIdx.y * 64;

    // --- loader assignments (lane-per-row => conflict-free transposed STS) ---
    const int arow = (w & 1) * 32 + l;          // 0..63 (tile row / tile gate col)
    int r = row0 + arow; if (r >= M) r = M - 1; // clamp for loads; stores guarded
    const int eidx = bwd ? neigh[r * KK + (KK - 1)] : neigh[r];
    const float4* asrc = (const float4*)(table + (size_t)eidx * FF);
    const float4* bsrc = (const float4*)(Wih + (size_t)(gate0 + arow) * FF);
    const int mb = (w >> 1) * 4;                // 4 float4 chunks per lane per pass

    const int lt = tid & 15, gt = tid >> 4;
    const int r0 = gt * 4;                      // micro-tile rows
    const int c0 = lt * 4;                      // micro-tile gates

    float acc[4][4];
    #pragma unroll
    for (int i = 0; i < 4; i++)
        #pragma unroll
        for (int j = 0; j < 4; j++) acc[i][j] = 0.f;

    #pragma unroll
    for (int p = 0; p < 2; p++) {
        // load tiles for this K-pass: global k = p*64 + kk
        #pragma unroll
        for (int m = 0; m < 4; m++) {
            float4 va = asrc[p * 16 + mb + m];
            float4 vb = bsrc[p * 16 + mb + m];
            int k0 = (mb + m) * 4;
            As[k0 + 0][arow] = va.x; As[k0 + 1][arow] = va.y;
            As[k0 + 2][arow] = va.z; As[k0 + 3][arow] = va.w;
            Bs[k0 + 0][arow] = vb.x; Bs[k0 + 1][arow] = vb.y;
            Bs[k0 + 2][arow] = vb.z; Bs[k0 + 3][arow] = vb.w;
        }
        __syncthreads();
        #pragma unroll 16
        for (int kk = 0; kk < 64; kk++) {
            float4 a = *(const float4*)&As[kk][r0];
            float4 b = *(const float4*)&Bs[kk][c0];
            acc[0][0] += a.x * b.x; acc[0][1] += a.x * b.y; acc[0][2] += a.x * b.z; acc[0][3] += a.x * b.w;
            acc[1][0] += a.y * b.x; acc[1][1] += a.y * b.y; acc[1][2] += a.y * b.z; acc[1][3] += a.y * b.w;
            acc[2][0] += a.z * b.x; acc[2][1] += a.z * b.y; acc[2][2] += a.z * b.z; acc[2][3] += a.z * b.w;
            acc[3][0] += a.w * b.x; acc[3][1] += a.w * b.y; acc[3][2] += a.w * b.z; acc[3][3] += a.w * b.w;
        }
        __syncthreads();
    }

    // epilogue: + (bih + bhh), store
    float bs[4];
    #pragma unroll
    for (int j = 0; j < 4; j++)
        bs[j] = bih[gate0 + c0 + j] + bhh[gate0 + c0 + j];

    #pragma unroll
    for (int i = 0; i < 4; i++) {
        int rr = row0 + r0 + i;
        if (rr < M) {
            float4 v = make_float4(acc[i][0] + bs[0], acc[i][1] + bs[1],
                                   acc[i][2] + bs[2], acc[i][3] + bs[3]);
            *(float4*)(outp + (size_t)rr * GG + gate0 + c0) = v;
        }
    }
}

// ---------------------------------------------------------------------------
// Kernel 2: forward LSTM recurrence (10 steps) + backward single-cell epilogue
// One block = 64 nodes. Whh^T in SMEM (Wt[j][g]), h in SMEM, c in registers.
// 256 threads: 16 hidden-groups (h0=4*lt) x 16 node-groups (n0=4*ng),
// each thread owns 4 nodes x 4 hidden units x 4 gate-quarters = 64 accumulators.
// ---------------------------------------------------------------------------
#define SMEM2 ((64*260 + 64*65) * 4)  // 83200 bytes

__global__ __launch_bounds__(256) void lstm_kernel(
    const float* __restrict__ Whh,
    float* __restrict__ out)
{
    extern __shared__ float sm[];
    float (*Wt)[260]  = (float(*)[260])sm;             // [64][260]: Wt[j][g] = Whh[g][j]
    float (*hbuf)[65] = (float(*)[65])(sm + 64 * 260); // [64 nodes][65]

    const int tid   = threadIdx.x;
    const int node0 = blockIdx.x * 64;

    // transpose-load Whh into SMEM
    for (int i = tid; i < GG * HH; i += 256) {
        int g = i >> 6, j = i & 63;
        Wt[j][g] = Whh[i];
    }
    __syncthreads();

    const int lt = tid & 15, ng = tid >> 4;
    const int h0 = lt * 4, n0 = ng * 4;

    float c[4][4];
    #pragma unroll
    for (int m = 0; m < 4; m++)
        #pragma unroll
        for (int i = 0; i < 4; i++) c[m][i] = 0.f;

    int nd[4];
    #pragma unroll
    for (int m = 0; m < 4; m++) {
        int n = node0 + n0 + m;
        nd[m] = n < NN ? n : NN - 1;   // clamp for loads; stores guarded
    }

    for (int k = 0; k < KK; k++) {
        // gates init = precomputed xg (includes both biases)
        float acc[4][4][4];
        #pragma unroll
        for (int m = 0; m < 4; m++) {
            const float* src = g_xg + ((size_t)nd[m] * KK + k) * GG;
            #pragma unroll
            for (int q = 0; q < 4; q++) {
                float4 v = *(const float4*)(src + q * 64 + h0);
                acc[m][q][0] = v.x; acc[m][q][1] = v.y;
                acc[m][q][2] = v.z; acc[m][q][3] = v.w;
            }
        }
        // + Whh @ h_prev  (skip at k=0: h_prev = 0)
        if (k > 0) {
            #pragma unroll 4
            for (int j = 0; j < HH; j++) {
                float hv[4];
                #pragma unroll
                for (int m = 0; m < 4; m++) hv[m] = hbuf[n0 + m][j];
                #pragma unroll
                for (int q = 0; q < 4; q++) {
                    float4 wv = *(const float4*)&Wt[j][q * 64 + h0];
                    #pragma unroll
                    for (int m = 0; m < 4; m++) {
                        acc[m][q][0] += wv.x * hv[m];
                        acc[m][q][1] += wv.y * hv[m];
                        acc[m][q][2] += wv.z * hv[m];
                        acc[m][q][3] += wv.w * hv[m];
                    }
                }
            }
        }
        __syncthreads();  // all reads of h_prev done before overwrite
        #pragma unroll
        for (int m = 0; m < 4; m++) {
            #pragma unroll
            for (int i = 0; i < 4; i++) {
                float ig = sigf(acc[m][0][i]);
                float fg = sigf(acc[m][1][i]);
                float gg = tanh_fast(acc[m][2][i]);
                float og = sigf(acc[m][3][i]);
                c[m][i] = fg * c[m][i] + ig * gg;
                hbuf[n0 + m][h0 + i] = og * tanh_fast(c[m][i]);
            }
        }
        __syncthreads();  // h_new visible to all before next step
    }

    // write forward hidden: out[n][0:64]
    for (int i = tid; i < 64 * HH; i += 256) {
        int nn = i >> 6, hh = i & 63;
        int n = node0 + nn;
        if (n < NN) out[(size_t)n * (2 * HH) + hh] = hbuf[nn][hh];
    }
    // backward direction: single cell on x[:, K-1] with h0=c0=0 -> out[n][64:128]
    for (int i = tid; i < 64 * HH; i += 256) {
        int nn = i >> 6, hh = i & 63;
        int n = node0 + nn;
        if (n < NN) {
            const float* s = g_xgb + (size_t)n * GG;
            float ig = sigf(s[hh]);
            float gg = tanh_fast(s[128 + hh]);
            float og = sigf(s[192 + hh]);
            float cc = ig * gg;
            out[(size_t)n * (2 * HH) + HH + hh] = og * tanh_fast(cc);
        }
    }
}

// ---------------------------------------------------------------------------
// Launch. Input order per metadata:
// 0 neigh_idx[N,K] i32, 1 embed_table[V,F] f32,
// 2 Wih_f[256,128], 3 Whh_f[256,64], 4 bih_f[256], 5 bhh_f[256],
// 6 Wih_b[256,128], 7 Whh_b[256,64], 8 bih_b[256], 9 bhh_b[256]
// out: [N, 128] f32
// ---------------------------------------------------------------------------
extern "C" void kernel_launch(void* const* d_in, const int* in_sizes, int n_in,
                              void* d_out, int out_size)
{
    const int*   neigh  = (const int*)  d_in[0];
    const float* table  = (const float*)d_in[1];
    const float* Wih_f  = (const float*)d_in[2];
    const float* Whh_f  = (const float*)d_in[3];
    const float* bih_f  = (const float*)d_in[4];
    const float* bhh_f  = (const float*)d_in[5];
    const float* Wih_b  = (const float*)d_in[6];
    const float* bih_b  = (const float*)d_in[8];
    const float* bhh_b  = (const float*)d_in[9];
    float* out = (float*)d_out;

    (void)in_sizes; (void)n_in; (void)out_size; (void)d_in;

    // forward projections: [500000, 128] x [128, 256]
    dim3 gf((MF + 63) / 64, 4);
    proj_kernel<<<gf, 256>>>(neigh, table, Wih_f, bih_f, bhh_f, MF, 0);

    // backward last-step projections: [50000, 128] x [128, 256]
    dim3 gb((NN + 63) / 64, 4);
    proj_kernel<<<gb, 256>>>(neigh, table, Wih_b, bih_b, bhh_b, NN, 1);

    // recurrence + output assembly
    cudaFuncSetAttribute(lstm_kernel, cudaFuncAttributeMaxDynamicSharedMemorySize, SMEM2);
    lstm_kernel<<<(NN + 63) / 64, 256, SMEM2>>>(Whh_f, out);
}

// round 12
// speedup vs baseline: 1.1916x; 1.1916x over previous
#include <cuda_runtime.h>
#include <cuda_bf16.h>
#include <math.h>
#include <stdint.h>

// Problem dims (fixed by the dataset)
#define NN 50000   // nodes
#define KK 10      // sampled neighbors (sequence length)
#define FF 128     // input_dim
#define HH 64      // hidden per direction
#define GG 256     // 4*H gates
#define MF (NN*KK) // 500000 projection rows (forward)

// Scratch (device globals — no allocation allowed)
__device__ float g_xg [(size_t)MF * GG];  // [N*K, 256] forward input projections (+bias)
__device__ float g_xgb[(size_t)NN * GG];  // [N, 256]   backward-last-step projections (+bias)
// bf16 hi/lo split weight copies: [0]=forward Wih, [1]=backward Wih
__device__ __nv_bfloat16 g_Wh[2][GG * FF];
__device__ __nv_bfloat16 g_Wl[2][GG * FF];

__device__ __forceinline__ float sigf(float x) {
    return 1.f / (1.f + __expf(-x));
}
__device__ __forceinline__ float tanh_fast(float x) {
    float e = __expf(2.f * x);
    return 1.f - 2.f / (e + 1.f);
}

// warp-level bf16 HMMA (portable PTX, no sm_103a-only features)
__device__ __forceinline__ void mma16816(float* c, const uint32_t* a,
                                         uint32_t b0, uint32_t b1) {
    asm volatile(
        "mma.sync.aligned.m16n8k16.row.col.f32.bf16.bf16.f32 "
        "{%0,%1,%2,%3}, {%4,%5,%6,%7}, {%8,%9}, {%0,%1,%2,%3};"
        : "+f"(c[0]), "+f"(c[1]), "+f"(c[2]), "+f"(c[3])
        : "r"(a[0]), "r"(a[1]), "r"(a[2]), "r"(a[3]), "r"(b0), "r"(b1));
}

// ---------------------------------------------------------------------------
// Kernel 0: split fp32 weights into bf16 hi/lo once
// ---------------------------------------------------------------------------
__global__ void conv_w_kernel(const float* __restrict__ Wf, const float* __restrict__ Wb) {
    int i = blockIdx.x * blockDim.x + threadIdx.x;
    if (i < GG * FF) {
        float x = Wf[i];
        __nv_bfloat16 h = __float2bfloat16(x);
        g_Wh[0][i] = h;
        g_Wl[0][i] = __float2bfloat16(x - __bfloat162float(h));
        x = Wb[i];
        h = __float2bfloat16(x);
        g_Wh[1][i] = h;
        g_Wl[1][i] = __float2bfloat16(x - __bfloat162float(h));
    }
}

// ---------------------------------------------------------------------------
// Kernel 1: gathered projection GEMM on HMMA (bf16 hi/lo split, fp32 acc)
//   out[r][g] = sum_f table[idx(r)][f] * Wih[g][f] + bih[g] + bhh[g]
// CTA: 512 threads (16 warps), M=128 gathered rows, N=256 gates, K=128.
// SMEM (u32 views, row stride 68 u32 = 136 bf16, +8 pad -> conflict-free frags):
//   AH [128][68], AL [128][68], BH [256][68], BL [256][68]  (204 KB)
// Warp tile 32x64: warps (wm = w&3) x (wn = w>>2); acc[2][8][4] = 64 f32 regs.
// 3 passes: Ahi*Bhi + Alo*Bhi + Ahi*Blo  (drops ~2^-16 lo*lo term).
// ---------------------------------------------------------------------------
#define RSU 68                         // row stride in u32 (64 data + 4 pad)
#define AH_OFF 0
#define AL_OFF (128 * RSU)
#define BH_OFF (2 * 128 * RSU)
#define BL_OFF (2 * 128 * RSU + 256 * RSU)
#define PROJ_SMEM ((2 * 128 * RSU + 2 * 256 * RSU) * 4)   // 208896 B

__global__ __launch_bounds__(512, 1) void proj_mma_kernel(
    const int*   __restrict__ neigh,
    const float* __restrict__ table,
    const float* __restrict__ bih,
    const float* __restrict__ bhh,
    int M, int bwd)
{
    extern __shared__ uint32_t smu[];
    uint32_t* AH = smu + AH_OFF;
    uint32_t* AL = smu + AL_OFF;
    uint32_t* BH = smu + BH_OFF;
    uint32_t* BL = smu + BL_OFF;

    const int tid  = threadIdx.x;
    const int row0 = blockIdx.x * 128;
    float* outp = bwd ? g_xgb : g_xg;

    // ---- A: gather 128 rows, split fp32 -> bf16 hi/lo (4 threads / row) ----
    {
        const int r_l = tid >> 2;          // local row 0..127
        const int q   = tid & 3;           // quarter: cols [32q, 32q+32)
        int r = row0 + r_l; if (r >= M) r = M - 1;
        const int e = bwd ? neigh[r * KK + (KK - 1)] : neigh[r];
        const float4* src = (const float4*)(table + (size_t)e * FF) + q * 8;
        uint32_t* ah = AH + r_l * RSU + q * 16;
        uint32_t* al = AL + r_l * RSU + q * 16;
        #pragma unroll
        for (int j = 0; j < 8; j++) {
            float4 v = src[j];
            __nv_bfloat16 h0 = __float2bfloat16(v.x);
            __nv_bfloat16 h1 = __float2bfloat16(v.y);
            __nv_bfloat16 h2 = __float2bfloat16(v.z);
            __nv_bfloat16 h3 = __float2bfloat16(v.w);
            __nv_bfloat16 l0 = __float2bfloat16(v.x - __bfloat162float(h0));
            __nv_bfloat16 l1 = __float2bfloat16(v.y - __bfloat162float(h1));
            __nv_bfloat16 l2 = __float2bfloat16(v.z - __bfloat162float(h2));
            __nv_bfloat16 l3 = __float2bfloat16(v.w - __bfloat162float(h3));
            ah[j * 2 + 0] = ((uint32_t)__bfloat16_as_ushort(h1) << 16) | __bfloat16_as_ushort(h0);
            ah[j * 2 + 1] = ((uint32_t)__bfloat16_as_ushort(h3) << 16) | __bfloat16_as_ushort(h2);
            al[j * 2 + 0] = ((uint32_t)__bfloat16_as_ushort(l1) << 16) | __bfloat16_as_ushort(l0);
            al[j * 2 + 1] = ((uint32_t)__bfloat16_as_ushort(l3) << 16) | __bfloat16_as_ushort(l2);
        }
    }

    // ---- B: pre-split bf16 weights -> SMEM (2 threads / gate row) ----
    {
        const int row  = tid >> 1;         // gate 0..255
        const int half = tid & 1;          // cols [64h, 64h+64)
        const uint4* wh = (const uint4*)(g_Wh[bwd] + row * FF) + half * 8;
        const uint4* wl = (const uint4*)(g_Wl[bwd] + row * FF) + half * 8;
        uint32_t* bh = BH + row * RSU + half * 32;
        uint32_t* bl = BL + row * RSU + half * 32;
        #pragma unroll
        for (int j = 0; j < 8; j++) {
            uint4 vh = wh[j], vl = wl[j];
            bh[j * 4 + 0] = vh.x; bh[j * 4 + 1] = vh.y;
            bh[j * 4 + 2] = vh.z; bh[j * 4 + 3] = vh.w;
            bl[j * 4 + 0] = vl.x; bl[j * 4 + 1] = vl.y;
            bl[j * 4 + 2] = vl.z; bl[j * 4 + 3] = vl.w;
        }
    }
    __syncthreads();

    // ---- MMA mainloop ----
    const int w  = tid >> 5;
    const int l  = tid & 31;
    const int wm = w & 3;                  // m-tile (32 rows each)
    const int wn = w >> 2;                 // n-tile (64 cols each)
    const int lr = l >> 2, lc = l & 3;

    float acc[2][8][4];
    #pragma unroll
    for (int mi = 0; mi < 2; mi++)
        #pragma unroll
        for (int ni = 0; ni < 8; ni++)
            #pragma unroll
            for (int i = 0; i < 4; i++) acc[mi][ni][i] = 0.f;

    #pragma unroll
    for (int t = 0; t < 3; t++) {
        const uint32_t* Ab = (t == 1) ? AL : AH;
        const uint32_t* Bb = (t == 2) ? BL : BH;
        #pragma unroll
        for (int ks = 0; ks < 8; ks++) {
            const int kb = ks * 8;         // u32 col base within row
            uint32_t a[2][4];
            #pragma unroll
            for (int mi = 0; mi < 2; mi++) {
                const int br = wm * 32 + mi * 16 + lr;
                a[mi][0] = Ab[(br    ) * RSU + kb     + lc];
                a[mi][1] = Ab[(br + 8) * RSU + kb     + lc];
                a[mi][2] = Ab[(br    ) * RSU + kb + 4 + lc];
                a[mi][3] = Ab[(br + 8) * RSU + kb + 4 + lc];
            }
            #pragma unroll
            for (int ni = 0; ni < 8; ni++) {
                const int n = wn * 64 + ni * 8 + lr;
                uint32_t b0 = Bb[n * RSU + kb + lc];
                uint32_t b1 = Bb[n * RSU + kb + 4 + lc];
                mma16816(acc[0][ni], a[0], b0, b1);
                mma16816(acc[1][ni], a[1], b0, b1);
            }
        }
    }

    // ---- epilogue: +bias, store float2 pairs ----
    float2 bb[8];
    #pragma unroll
    for (int ni = 0; ni < 8; ni++) {
        int c = wn * 64 + ni * 8 + lc * 2;
        bb[ni].x = bih[c] + bhh[c];
        bb[ni].y = bih[c + 1] + bhh[c + 1];
    }
    #pragma unroll
    for (int mi = 0; mi < 2; mi++) {
        const int r = row0 + wm * 32 + mi * 16 + lr;
        #pragma unroll
        for (int ni = 0; ni < 8; ni++) {
            const int c = wn * 64 + ni * 8 + lc * 2;
            if (r < M) {
                float2 v0 = make_float2(acc[mi][ni][0] + bb[ni].x,
                                        acc[mi][ni][1] + bb[ni].y);
                *(float2*)(outp + (size_t)r * GG + c) = v0;
            }
            if (r + 8 < M) {
                float2 v1 = make_float2(acc[mi][ni][2] + bb[ni].x,
                                        acc[mi][ni][3] + bb[ni].y);
                *(float2*)(outp + (size_t)(r + 8) * GG + c) = v1;
            }
        }
    }
}

// ---------------------------------------------------------------------------
// Kernel 2: forward LSTM recurrence (10 steps) + backward single-cell epilogue
// (unchanged — one block = 64 nodes, Whh^T + h in SMEM, c in regs)
// ---------------------------------------------------------------------------
#define SMEM2 ((64*260 + 64*65) * 4)  // 83200 bytes

__global__ __launch_bounds__(256) void lstm_kernel(
    const float* __restrict__ Whh,
    float* __restrict__ out)
{
    extern __shared__ float smf[];
    float (*Wt)[260]  = (float(*)[260])smf;
    float (*hbuf)[65] = (float(*)[65])(smf + 64 * 260);

    const int tid   = threadIdx.x;
    const int node0 = blockIdx.x * 64;

    for (int i = tid; i < GG * HH; i += 256) {
        int g = i >> 6, j = i & 63;
        Wt[j][g] = Whh[i];
    }
    __syncthreads();

    const int lt = tid & 15, ng = tid >> 4;
    const int h0 = lt * 4, n0 = ng * 4;

    float c[4][4];
    #pragma unroll
    for (int m = 0; m < 4; m++)
        #pragma unroll
        for (int i = 0; i < 4; i++) c[m][i] = 0.f;

    int nd[4];
    #pragma unroll
    for (int m = 0; m < 4; m++) {
        int n = node0 + n0 + m;
        nd[m] = n < NN ? n : NN - 1;
    }

    for (int k = 0; k < KK; k++) {
        float acc[4][4][4];
        #pragma unroll
        for (int m = 0; m < 4; m++) {
            const float* src = g_xg + ((size_t)nd[m] * KK + k) * GG;
            #pragma unroll
            for (int q = 0; q < 4; q++) {
                float4 v = *(const float4*)(src + q * 64 + h0);
                acc[m][q][0] = v.x; acc[m][q][1] = v.y;
                acc[m][q][2] = v.z; acc[m][q][3] = v.w;
            }
        }
        if (k > 0) {
            #pragma unroll 4
            for (int j = 0; j < HH; j++) {
                float hv[4];
                #pragma unroll
                for (int m = 0; m < 4; m++) hv[m] = hbuf[n0 + m][j];
                #pragma unroll
                for (int q = 0; q < 4; q++) {
                    float4 wv = *(const float4*)&Wt[j][q * 64 + h0];
                    #pragma unroll
                    for (int m = 0; m < 4; m++) {
                        acc[m][q][0] += wv.x * hv[m];
                        acc[m][q][1] += wv.y * hv[m];
                        acc[m][q][2] += wv.z * hv[m];
                        acc[m][q][3] += wv.w * hv[m];
                    }
                }
            }
        }
        __syncthreads();
        #pragma unroll
        for (int m = 0; m < 4; m++) {
            #pragma unroll
            for (int i = 0; i < 4; i++) {
                float ig = sigf(acc[m][0][i]);
                float fg = sigf(acc[m][1][i]);
                float gg = tanh_fast(acc[m][2][i]);
                float og = sigf(acc[m][3][i]);
                c[m][i] = fg * c[m][i] + ig * gg;
                hbuf[n0 + m][h0 + i] = og * tanh_fast(c[m][i]);
            }
        }
        __syncthreads();
    }

    for (int i = tid; i < 64 * HH; i += 256) {
        int nn = i >> 6, hh = i & 63;
        int n = node0 + nn;
        if (n < NN) out[(size_t)n * (2 * HH) + hh] = hbuf[nn][hh];
    }
    for (int i = tid; i < 64 * HH; i += 256) {
        int nn = i >> 6, hh = i & 63;
        int n = node0 + nn;
        if (n < NN) {
            const float* s = g_xgb + (size_t)n * GG;
            float ig = sigf(s[hh]);
            float gg = tanh_fast(s[128 + hh]);
            float og = sigf(s[192 + hh]);
            float cc = ig * gg;
            out[(size_t)n * (2 * HH) + HH + hh] = og * tanh_fast(cc);
        }
    }
}

// ---------------------------------------------------------------------------
// Launch. Input order per metadata:
// 0 neigh_idx[N,K] i32, 1 embed_table[V,F] f32,
// 2 Wih_f[256,128], 3 Whh_f[256,64], 4 bih_f[256], 5 bhh_f[256],
// 6 Wih_b[256,128], 7 Whh_b[256,64], 8 bih_b[256], 9 bhh_b[256]
// out: [N, 128] f32
// ---------------------------------------------------------------------------
extern "C" void kernel_launch(void* const* d_in, const int* in_sizes, int n_in,
                              void* d_out, int out_size)
{
    const int*   neigh  = (const int*)  d_in[0];
    const float* table  = (const float*)d_in[1];
    const float* Wih_f  = (const float*)d_in[2];
    const float* Whh_f  = (const float*)d_in[3];
    const float* bih_f  = (const float*)d_in[4];
    const float* bhh_f  = (const float*)d_in[5];
    const float* Wih_b  = (const float*)d_in[6];
    const float* bih_b  = (const float*)d_in[8];
    const float* bhh_b  = (const float*)d_in[9];
    float* out = (float*)d_out;

    (void)in_sizes; (void)n_in; (void)out_size;

    // 0) split weights into bf16 hi/lo
    conv_w_kernel<<<128, 256>>>(Wih_f, Wih_b);

    // 1) HMMA gathered projections
    cudaFuncSetAttribute(proj_mma_kernel,
                         cudaFuncAttributeMaxDynamicSharedMemorySize, PROJ_SMEM);
    proj_mma_kernel<<<(MF + 127) / 128, 512, PROJ_SMEM>>>(neigh, table, bih_f, bhh_f, MF, 0);
    proj_mma_kernel<<<(NN + 127) / 128, 512, PROJ_SMEM>>>(neigh, table, bih_b, bhh_b, NN, 1);

    // 2) recurrence + output assembly
    cudaFuncSetAttribute(lstm_kernel, cudaFuncAttributeMaxDynamicSharedMemorySize, SMEM2);
    lstm_kernel<<<(NN + 63) / 64, 256, SMEM2>>>(Whh_f, out);
}